// round 12
// baseline (speedup 1.0000x reference)
#include <cuda_runtime.h>
#include <cuda_fp16.h>
#include <math.h>
#include <stdint.h>

#define T_TOK 4096
#define DDIM  2048
#define NEXP  8
#define FDIM  512
#define CAP   4096
#define BM    128
#define BN    128       // down-GEMM N tile
#define BNF   64        // fused up-GEMM N tile
#define BKH   32        // K-chunk in halves (= 64 bytes per row)
#define SPAD  20        // smem row stride in uint32 (16 data + 4 pad)
#define SBUF  (BM * SPAD * 4)    // down: one stage bytes = 10240
#define SBUFA (BM * SPAD * 4)    // fused A stage bytes = 10240
#define SBUFB (BNF * SPAD * 4)   // fused B stage bytes = 5120

// ---------------------------------------------------------------------------
// Scratch (device globals; allocation is forbidden)
// ---------------------------------------------------------------------------
__device__ __half g_h16 [(size_t)T_TOK * DDIM];
__device__ __half g_w0h [(size_t)NEXP * FDIM * DDIM];
__device__ __half g_w1h [(size_t)NEXP * FDIM * DDIM];
__device__ __half g_woh [(size_t)NEXP * DDIM * FDIM];
__device__ __half g_sw0h[(size_t)FDIM * DDIM];
__device__ __half g_sw1h[(size_t)FDIM * DDIM];
__device__ __half g_swoh[(size_t)DDIM * FDIM];
__device__ __half g_ih  [(size_t)NEXP * CAP * FDIM];   // routed silu(g)*u
__device__ __half g_sih [(size_t)T_TOK * FDIM];        // shared silu(g)*u
__device__ int    g_cnt[NEXP];
__device__ int    g_tok[NEXP * CAP];
__device__ float  g_wt[NEXP * CAP];
__device__ float  g_gate[T_TOK];

__device__ __forceinline__ uint32_t su32(const void* p) {
    uint32_t a;
    asm("{ .reg .u64 t; cvta.to.shared.u64 t, %1; cvt.u32.u64 %0, t; }" : "=r"(a) : "l"(p));
    return a;
}
__device__ __forceinline__ void cpasync16(uint32_t dst, const void* src) {
    asm volatile("cp.async.cg.shared.global [%0], [%1], 16;" :: "r"(dst), "l"(src) : "memory");
}
#define CP_COMMIT() asm volatile("cp.async.commit_group;" ::: "memory")
#define CP_WAIT(n)  asm volatile("cp.async.wait_group %0;" :: "n"(n) : "memory")

__device__ __forceinline__ void ldsm4(uint32_t* r, uint32_t addr) {
    asm volatile("ldmatrix.sync.aligned.m8n8.x4.shared.b16 {%0,%1,%2,%3}, [%4];"
        : "=r"(r[0]), "=r"(r[1]), "=r"(r[2]), "=r"(r[3]) : "r"(addr));
}
__device__ __forceinline__ void ldsm2(uint32_t* r, uint32_t addr) {
    asm volatile("ldmatrix.sync.aligned.m8n8.x2.shared.b16 {%0,%1}, [%2];"
        : "=r"(r[0]), "=r"(r[1]) : "r"(addr));
}

__device__ __forceinline__ void mma16(float* d, const uint32_t* a, const uint32_t* b) {
    asm volatile(
        "mma.sync.aligned.m16n8k16.row.col.f32.f16.f16.f32 "
        "{%0,%1,%2,%3}, {%4,%5,%6,%7}, {%8,%9}, {%0,%1,%2,%3};"
        : "+f"(d[0]), "+f"(d[1]), "+f"(d[2]), "+f"(d[3])
        : "r"(a[0]), "r"(a[1]), "r"(a[2]), "r"(a[3]), "r"(b[0]), "r"(b[1]));
}
__device__ __forceinline__ float silu(float x) {
    return x / (1.f + expf(-x));
}

// ---------------------------------------------------------------------------
__global__ void zero_counts_kernel() {
    if (threadIdx.x < NEXP) g_cnt[threadIdx.x] = 0;
}

// fp32 -> fp16 conversion (RN), float4-vectorized
__global__ void cvt_half_kernel(const float* __restrict__ in, __half* __restrict__ out) {
    size_t i = (size_t)blockIdx.x * 256 + threadIdx.x;   // float4 index
    float4 v = ((const float4*)in)[i];
    ((__half2*)out)[i * 2]     = __floats2half2_rn(v.x, v.y);
    ((__half2*)out)[i * 2 + 1] = __floats2half2_rn(v.z, v.w);
}

// ---------------------------------------------------------------------------
// Router: 1 warp per token. Also emits fp16 copy of h (fused conversion).
// ---------------------------------------------------------------------------
__global__ void router_kernel(const float* __restrict__ h,
                              const float* __restrict__ gate_w,
                              const float* __restrict__ sg_w,
                              float* __restrict__ logits_out) {
    int warp = threadIdx.x >> 5;
    int lane = threadIdx.x & 31;
    int t = blockIdx.x * 4 + warp;
    if (t >= T_TOK) return;

    float acc[9];
#pragma unroll
    for (int i = 0; i < 9; i++) acc[i] = 0.f;

    const float4* hp = (const float4*)(h + (size_t)t * DDIM);
    __half2* hp16 = (__half2*)(g_h16 + (size_t)t * DDIM);
    for (int d = lane; d < DDIM / 4; d += 32) {
        float4 hv = hp[d];
        hp16[d * 2]     = __floats2half2_rn(hv.x, hv.y);
        hp16[d * 2 + 1] = __floats2half2_rn(hv.z, hv.w);
#pragma unroll
        for (int e = 0; e < NEXP; e++) {
            float4 w = ((const float4*)(gate_w + (size_t)e * DDIM))[d];
            acc[e] += hv.x * w.x + hv.y * w.y + hv.z * w.z + hv.w * w.w;
        }
        float4 w = ((const float4*)sg_w)[d];
        acc[8] += hv.x * w.x + hv.y * w.y + hv.z * w.z + hv.w * w.w;
    }
#pragma unroll
    for (int i = 0; i < 9; i++) {
#pragma unroll
        for (int off = 16; off > 0; off >>= 1)
            acc[i] += __shfl_down_sync(0xffffffffu, acc[i], off);
    }

    if (lane == 0) {
        if (logits_out) {
#pragma unroll
            for (int e = 0; e < NEXP; e++) logits_out[t * NEXP + e] = acc[e];
        }
        int i0 = 0;
#pragma unroll
        for (int e = 1; e < NEXP; e++) if (acc[e] > acc[i0]) i0 = e;
        int i1 = (i0 == 0) ? 1 : 0;
#pragma unroll
        for (int e = 0; e < NEXP; e++) if (e != i0 && e != i1 && acc[e] > acc[i1]) i1 = e;

        float wA = 1.f / (1.f + expf(acc[i1] - acc[i0]));
        float wB = 1.f - wA;

        int s0 = atomicAdd(&g_cnt[i0], 1);
        g_tok[i0 * CAP + s0] = t;  g_wt[i0 * CAP + s0] = wA;
        int s1 = atomicAdd(&g_cnt[i1], 1);
        g_tok[i1 * CAP + s1] = t;  g_wt[i1 * CAP + s1] = wB;

        g_gate[t] = 1.f / (1.f + expf(-acc[8]));
    }
}

// ---------------------------------------------------------------------------
// FUSED up-projection: one pass computes g = A*W0^T+b0 AND u = A*W1^T+b1,
// then writes fp16 silu(g)*u. g/u live only in registers (fp32).
// CTA tile 128(M) x 64(N), 256 threads = 8 warps (4x2), warp tile 32x32 dual.
// Fragment loads via ldmatrix (bit-identical mapping to prior scalar loads).
// ---------------------------------------------------------------------------
template<bool ROUTED>
__global__ void __launch_bounds__(256, 2)
upfused_h(const __half* __restrict__ A,
          const __half* __restrict__ W0g, const float* __restrict__ B0v,
          const __half* __restrict__ W1g, const float* __restrict__ B1v) {
    constexpr int NT = DDIM / BKH;   // 64
    const int e  = ROUTED ? blockIdx.z : 0;
    const int Ne = ROUTED ? g_cnt[e] : T_TOK;
    const int row0 = blockIdx.y * BM;
    if (row0 >= Ne) return;
    const int n0  = blockIdx.x * BNF;
    const int tid  = threadIdx.x;
    const int lane = tid & 31;
    const int wid  = tid >> 5;
    const int wm   = (wid >> 1) * 32;   // 4 warp-rows over M=128
    const int wn   = (wid & 1) * 32;    // 2 warp-cols over N=64

    __shared__ uint32_t As [2][BM][SPAD];
    __shared__ uint32_t Bs0[2][BNF][SPAD];
    __shared__ uint32_t Bs1[2][BNF][SPAD];
    __shared__ int sTok[BM];

    if (ROUTED) {
        if (tid < BM) {
            int r = row0 + tid;
            sTok[tid] = g_tok[e * CAP + ((r < Ne) ? r : (Ne - 1))];
        }
        __syncthreads();
    }

    const __half* W0b = ROUTED ? (W0g + (size_t)e * FDIM * DDIM) : W0g;
    const __half* W1b = ROUTED ? (W1g + (size_t)e * FDIM * DDIM) : W1g;

    float acc0[2][4][4], acc1[2][4][4];
#pragma unroll
    for (int i = 0; i < 2; i++)
#pragma unroll
        for (int j = 0; j < 4; j++)
#pragma unroll
            for (int r = 0; r < 4; r++) { acc0[i][j][r] = 0.f; acc1[i][j][r] = 0.f; }

    // staging: A = 512 chunks (2/thread), B0/B1 = 256 chunks (1/thread)
    const __half* aptr[2];
    uint32_t dAs[2];
#pragma unroll
    for (int i = 0; i < 2; i++) {
        int idx = i * 256 + tid;
        int r  = idx >> 2;
        int ch = (idx & 3) * 8;
        aptr[i] = ROUTED ? (A + (size_t)sTok[r] * DDIM + ch)
                         : (A + (size_t)(row0 + r) * DDIM + ch);
        dAs[i]  = su32(&As[0][r][(idx & 3) * 4]);
    }
    const int br  = tid >> 2;          // 0..63
    const int bch = (tid & 3) * 8;
    const __half* b0ptr = W0b + (size_t)(n0 + br) * DDIM + bch;
    const __half* b1ptr = W1b + (size_t)(n0 + br) * DDIM + bch;
    const uint32_t dB0 = su32(&Bs0[0][br][(tid & 3) * 4]);
    const uint32_t dB1 = su32(&Bs1[0][br][(tid & 3) * 4]);

    // ldmatrix per-lane source addresses (buf 0; buf 1 = + fixed offset)
    // A x4: lanes 0-7 rows rb+0..7 col 0; 8-15 rows rb+8..15 col 0;
    //       16-23 rows rb+0..7 col+4; 24-31 rows rb+8..15 col+4
    const int aRow = (lane & 7) + ((lane >> 3) & 1) * 8;
    const int aCol = (lane >> 4) * 4;
    // B x2: lanes 0-7 rows nb+0..7 col 0; 8-15 rows nb+0..7 col+4
    const int bRow = lane & 7;
    const int bCol = ((lane >> 3) & 1) * 4;

    // prologue
#pragma unroll
    for (int i = 0; i < 2; i++) cpasync16(dAs[i], aptr[i]);
    cpasync16(dB0, b0ptr);
    cpasync16(dB1, b1ptr);
    CP_COMMIT();

    for (int it = 0; it < NT; it++) {
        const int buf = it & 1;
        if (it + 1 < NT) {
            const int nbuf = (it + 1) & 1;
            const int koff = (it + 1) * BKH;
#pragma unroll
            for (int i = 0; i < 2; i++) cpasync16(dAs[i] + nbuf * SBUFA, aptr[i] + koff);
            cpasync16(dB0 + nbuf * SBUFB, b0ptr + koff);
            cpasync16(dB1 + nbuf * SBUFB, b1ptr + koff);
            CP_COMMIT();
            CP_WAIT(1);
        } else {
            CP_WAIT(0);
        }
        __syncthreads();

#pragma unroll
        for (int ks = 0; ks < 2; ks++) {
            const int base = ks * 8;
            uint32_t af[2][4], bf0[4][2], bf1[4][2];
#pragma unroll
            for (int im = 0; im < 2; im++) {
                int rb = wm + im * 16;
                ldsm4(af[im], su32(&As[buf][rb + aRow][base + aCol]));
            }
#pragma unroll
            for (int in = 0; in < 4; in++) {
                int nb = wn + in * 8;
                ldsm2(bf0[in], su32(&Bs0[buf][nb + bRow][base + bCol]));
                ldsm2(bf1[in], su32(&Bs1[buf][nb + bRow][base + bCol]));
            }
#pragma unroll
            for (int im = 0; im < 2; im++)
#pragma unroll
                for (int in = 0; in < 4; in++) {
                    mma16(acc0[im][in], af[im], bf0[in]);
                    mma16(acc1[im][in], af[im], bf1[in]);
                }
        }
        __syncthreads();
    }

    // ---- epilogue: SwiGLU fully in registers, fp16 out ----
    const float* b0p = ROUTED ? (B0v + e * FDIM) : B0v;
    const float* b1p = ROUTED ? (B1v + e * FDIM) : B1v;
#pragma unroll
    for (int im = 0; im < 2; im++) {
#pragma unroll
        for (int in = 0; in < 4; in++) {
            const int c0 = n0 + wn + in * 8 + 2 * (lane & 3);
            const float g_b0 = b0p[c0], g_b1 = b0p[c0 + 1];
            const float u_b0 = b1p[c0], u_b1 = b1p[c0 + 1];
#pragma unroll
            for (int hr = 0; hr < 2; hr++) {
                int r = wm + im * 16 + (lane >> 2) + hr * 8;
                if (row0 + r >= Ne) continue;
                float gg0 = acc0[im][in][hr * 2 + 0] + g_b0;
                float gg1 = acc0[im][in][hr * 2 + 1] + g_b1;
                float uu0 = acc1[im][in][hr * 2 + 0] + u_b0;
                float uu1 = acc1[im][in][hr * 2 + 1] + u_b1;
                float r0 = silu(gg0) * uu0;
                float r1 = silu(gg1) * uu1;
                if (ROUTED) {
                    size_t idx = ((size_t)e * CAP + row0 + r) * FDIM + c0;
                    *(__half2*)(g_ih + idx) = __floats2half2_rn(r0, r1);
                } else {
                    size_t idx = (size_t)(row0 + r) * FDIM + c0;
                    *(__half2*)(g_sih + idx) = __floats2half2_rn(r0, r1);
                }
            }
        }
    }
}

// ---------------------------------------------------------------------------
// Down-projection fp16 mma.sync GEMM (m16n8k16), cp.async 2-stage, ldmatrix.
// CTA 128x128, 256 threads = 8 warps (2x4), warp tile 64x32, K=FDIM.
// MODE 2: routed  A=g_ih;  atomicAdd(out[tok,d], wt*(acc+bo[e,d]))
// MODE 3: shared  A=g_sih; out[t,d] = gate[t]*(acc+sbo[d])
// ---------------------------------------------------------------------------
template<int MODE>
__global__ void __launch_bounds__(256, 2)
gemm_h(const __half* __restrict__ A, const __half* __restrict__ B,
       const float* __restrict__ bias, float* __restrict__ out) {
    constexpr int K  = FDIM;
    constexpr int NT = K / BKH;   // 16
    const int e  = (MODE == 2) ? blockIdx.z : 0;
    const int Ne = (MODE == 2) ? g_cnt[e] : T_TOK;
    const int row0 = blockIdx.y * BM;
    if (row0 >= Ne) return;
    const int n0  = blockIdx.x * BN;
    const int tid  = threadIdx.x;
    const int lane = tid & 31;
    const int wid  = tid >> 5;
    const int wm   = (wid >> 2) * 64;
    const int wn   = (wid & 3) * 32;

    __shared__ uint32_t As[2][BM][SPAD];
    __shared__ uint32_t Bs[2][BN][SPAD];
    __shared__ int   sTok[BM];
    __shared__ float sWt[BM];

    if (MODE == 2) {
        if (tid < BM) {
            int r = row0 + tid;
            int rr = (r < Ne) ? r : (Ne - 1);
            sTok[tid] = g_tok[e * CAP + rr];
            sWt[tid]  = g_wt[e * CAP + rr];
        }
        __syncthreads();
    }

    const __half* Bb = (MODE == 2) ? (B + (size_t)e * DDIM * FDIM) : B;

    float acc[4][4][4];
#pragma unroll
    for (int i = 0; i < 4; i++)
#pragma unroll
        for (int j = 0; j < 4; j++)
#pragma unroll
            for (int r = 0; r < 4; r++) acc[i][j][r] = 0.f;

    const __half* aptr[2];
    const __half* bptr[2];
    uint32_t      dA[2], dB[2];
#pragma unroll
    for (int i = 0; i < 2; i++) {
        int idx = i * 256 + tid;
        int r  = idx >> 2;
        int ch = (idx & 3) * 8;
        if (MODE == 2) aptr[i] = A + ((size_t)e * CAP + row0 + r) * FDIM + ch;
        else           aptr[i] = A + (size_t)(row0 + r) * FDIM + ch;
        bptr[i] = Bb + (size_t)(n0 + r) * K + ch;
        dA[i] = su32(&As[0][r][(idx & 3) * 4]);
        dB[i] = su32(&Bs[0][r][(idx & 3) * 4]);
    }

    const int aRow = (lane & 7) + ((lane >> 3) & 1) * 8;
    const int aCol = (lane >> 4) * 4;
    const int bRow = lane & 7;
    const int bCol = ((lane >> 3) & 1) * 4;

#pragma unroll
    for (int i = 0; i < 2; i++) {
        cpasync16(dA[i], aptr[i]);
        cpasync16(dB[i], bptr[i]);
    }
    CP_COMMIT();

    for (int it = 0; it < NT; it++) {
        const int buf = it & 1;
        if (it + 1 < NT) {
            const int nbuf = (it + 1) & 1;
            const int koff = (it + 1) * BKH;
#pragma unroll
            for (int i = 0; i < 2; i++) {
                cpasync16(dA[i] + nbuf * SBUF, aptr[i] + koff);
                cpasync16(dB[i] + nbuf * SBUF, bptr[i] + koff);
            }
            CP_COMMIT();
            CP_WAIT(1);
        } else {
            CP_WAIT(0);
        }
        __syncthreads();

#pragma unroll
        for (int ks = 0; ks < 2; ks++) {
            const int base = ks * 8;
            uint32_t af[4][4], bf[4][2];
#pragma unroll
            for (int im = 0; im < 4; im++) {
                int rb = wm + im * 16;
                ldsm4(af[im], su32(&As[buf][rb + aRow][base + aCol]));
            }
#pragma unroll
            for (int in = 0; in < 4; in++) {
                int nb = wn + in * 8;
                ldsm2(bf[in], su32(&Bs[buf][nb + bRow][base + bCol]));
            }
#pragma unroll
            for (int im = 0; im < 4; im++)
#pragma unroll
                for (int in = 0; in < 4; in++)
                    mma16(acc[im][in], af[im], bf[in]);
        }
        __syncthreads();
    }

    const float* bp = (MODE == 2) ? (bias + e * DDIM) : bias;
#pragma unroll
    for (int im = 0; im < 4; im++) {
#pragma unroll
        for (int in = 0; in < 4; in++) {
            const int c0 = n0 + wn + in * 8 + 2 * (lane & 3);
            const float b0v = bp[c0], b1v = bp[c0 + 1];
#pragma unroll
            for (int hr = 0; hr < 2; hr++) {
                int r = wm + im * 16 + (lane >> 2) + hr * 8;
                if (row0 + r >= Ne) continue;
                float v0 = acc[im][in][hr * 2 + 0] + b0v;
                float v1 = acc[im][in][hr * 2 + 1] + b1v;
                if (MODE == 2) {
                    int   t  = sTok[r];
                    float wt = sWt[r];
                    float* op = out + (size_t)t * DDIM + c0;
                    atomicAdd(op,     wt * v0);
                    atomicAdd(op + 1, wt * v1);
                } else {
                    float gate = g_gate[row0 + r];
                    *(float2*)(out + (size_t)(row0 + r) * DDIM + c0) =
                        make_float2(gate * v0, gate * v1);
                }
            }
        }
    }
}

// ---------------------------------------------------------------------------
extern "C" void kernel_launch(void* const* d_in, const int* in_sizes, int n_in,
                              void* d_out, int out_size) {
    const float* h      = (const float*)d_in[0];
    const float* gate_w = (const float*)d_in[1];
    const float* w0     = (const float*)d_in[2];
    const float* b0     = (const float*)d_in[3];
    const float* w1     = (const float*)d_in[4];
    const float* b1     = (const float*)d_in[5];
    const float* wo     = (const float*)d_in[6];
    const float* bo     = (const float*)d_in[7];
    const float* sw0    = (const float*)d_in[8];
    const float* sb0    = (const float*)d_in[9];
    const float* sw1    = (const float*)d_in[10];
    const float* sb1    = (const float*)d_in[11];
    const float* swo    = (const float*)d_in[12];
    const float* sbo    = (const float*)d_in[13];
    const float* sg_w   = (const float*)d_in[14];

    float* out = (float*)d_out;
    float* logits = nullptr;
    if ((size_t)out_size >= (size_t)T_TOK * DDIM + (size_t)T_TOK * NEXP)
        logits = out + (size_t)T_TOK * DDIM;

    __half *h16, *w0h, *w1h, *woh, *sw0h, *sw1h, *swoh, *ih, *sih;
    cudaGetSymbolAddress((void**)&h16,  g_h16);
    cudaGetSymbolAddress((void**)&w0h,  g_w0h);
    cudaGetSymbolAddress((void**)&w1h,  g_w1h);
    cudaGetSymbolAddress((void**)&woh,  g_woh);
    cudaGetSymbolAddress((void**)&sw0h, g_sw0h);
    cudaGetSymbolAddress((void**)&sw1h, g_sw1h);
    cudaGetSymbolAddress((void**)&swoh, g_swoh);
    cudaGetSymbolAddress((void**)&ih,   g_ih);
    cudaGetSymbolAddress((void**)&sih,  g_sih);

    zero_counts_kernel<<<1, 32>>>();
    router_kernel<<<T_TOK / 4, 128>>>(h, gate_w, sg_w, logits);   // also emits h16

    // weight fp32 -> fp16 conversion (bandwidth-bound)
    const unsigned NB_W = (unsigned)((size_t)NEXP * FDIM * DDIM / 4 / 256);
    const unsigned NB_S = (unsigned)((size_t)FDIM * DDIM / 4 / 256);
    cvt_half_kernel<<<NB_W, 256>>>(w0,  w0h);
    cvt_half_kernel<<<NB_W, 256>>>(w1,  w1h);
    cvt_half_kernel<<<NB_W, 256>>>(wo,  woh);
    cvt_half_kernel<<<NB_S, 256>>>(sw0, sw0h);
    cvt_half_kernel<<<NB_S, 256>>>(sw1, sw1h);
    cvt_half_kernel<<<NB_S, 256>>>(swo, swoh);

    // fused up projections (g and u in one pass, SwiGLU in registers)
    upfused_h<true> <<<dim3(FDIM / BNF, CAP / BM, NEXP), 256>>>(h16, w0h, b0, w1h, b1);
    upfused_h<false><<<dim3(FDIM / BNF, T_TOK / BM, 1), 256>>>(h16, sw0h, sb0, sw1h, sb1);

    // down projections: shared writes base, routed atomically accumulates
    gemm_h<3><<<dim3(DDIM / BN, T_TOK / BM, 1), 256>>>(sih, swoh, sbo, out);
    gemm_h<2><<<dim3(DDIM / BN, CAP / BM, NEXP), 256>>>(ih, woh, bo, out);
}

// round 14
// speedup vs baseline: 1.0305x; 1.0305x over previous
#include <cuda_runtime.h>
#include <cuda_fp16.h>
#include <math.h>
#include <stdint.h>

#define T_TOK 4096
#define DDIM  2048
#define NEXP  8
#define FDIM  512
#define CAP   4096
#define BM    128
#define BN    128       // down-GEMM N tile
#define BNF   64        // fused up-GEMM N tile
#define BKH   32        // K-chunk in halves (= 64 bytes per row)
#define SPAD  20        // smem row stride in uint32 (16 data + 4 pad)
#define NSTG  3         // pipeline stages
#define STGU  (BM * SPAD * 4 + 2 * BNF * SPAD * 4)   // up stage: A + B0 + B1 = 20480
#define STGD  (2 * BM * SPAD * 4)                    // down stage: A + B = 20480

// ---------------------------------------------------------------------------
// Scratch (device globals; allocation is forbidden)
// ---------------------------------------------------------------------------
__device__ __half g_h16 [(size_t)T_TOK * DDIM];
__device__ __half g_w0h [(size_t)NEXP * FDIM * DDIM];
__device__ __half g_w1h [(size_t)NEXP * FDIM * DDIM];
__device__ __half g_woh [(size_t)NEXP * DDIM * FDIM];
__device__ __half g_sw0h[(size_t)FDIM * DDIM];
__device__ __half g_sw1h[(size_t)FDIM * DDIM];
__device__ __half g_swoh[(size_t)DDIM * FDIM];
__device__ __half g_ih  [(size_t)NEXP * CAP * FDIM];   // routed silu(g)*u
__device__ __half g_sih [(size_t)T_TOK * FDIM];        // shared silu(g)*u
__device__ int    g_cnt[NEXP];
__device__ int    g_tok[NEXP * CAP];
__device__ float  g_wt[NEXP * CAP];
__device__ float  g_gate[T_TOK];

__device__ __forceinline__ uint32_t su32(const void* p) {
    uint32_t a;
    asm("{ .reg .u64 t; cvta.to.shared.u64 t, %1; cvt.u32.u64 %0, t; }" : "=r"(a) : "l"(p));
    return a;
}
__device__ __forceinline__ void cpasync16(uint32_t dst, const void* src) {
    asm volatile("cp.async.cg.shared.global [%0], [%1], 16;" :: "r"(dst), "l"(src) : "memory");
}
#define CP_COMMIT() asm volatile("cp.async.commit_group;" ::: "memory")
#define CP_WAIT1()  asm volatile("cp.async.wait_group 1;" ::: "memory")

__device__ __forceinline__ void mma16(float* d, const uint32_t* a, const uint32_t* b) {
    asm volatile(
        "mma.sync.aligned.m16n8k16.row.col.f32.f16.f16.f32 "
        "{%0,%1,%2,%3}, {%4,%5,%6,%7}, {%8,%9}, {%0,%1,%2,%3};"
        : "+f"(d[0]), "+f"(d[1]), "+f"(d[2]), "+f"(d[3])
        : "r"(a[0]), "r"(a[1]), "r"(a[2]), "r"(a[3]), "r"(b[0]), "r"(b[1]));
}
__device__ __forceinline__ float silu(float x) {
    return x / (1.f + expf(-x));
}

// ---------------------------------------------------------------------------
__global__ void zero_counts_kernel() {
    if (threadIdx.x < NEXP) g_cnt[threadIdx.x] = 0;
}

// fp32 -> fp16 conversion (RN), float4-vectorized
__global__ void cvt_half_kernel(const float* __restrict__ in, __half* __restrict__ out) {
    size_t i = (size_t)blockIdx.x * 256 + threadIdx.x;
    float4 v = ((const float4*)in)[i];
    ((__half2*)out)[i * 2]     = __floats2half2_rn(v.x, v.y);
    ((__half2*)out)[i * 2 + 1] = __floats2half2_rn(v.z, v.w);
}

// ---------------------------------------------------------------------------
// Router: 1 warp per token. Also emits fp16 copy of h (fused conversion).
// ---------------------------------------------------------------------------
__global__ void router_kernel(const float* __restrict__ h,
                              const float* __restrict__ gate_w,
                              const float* __restrict__ sg_w,
                              float* __restrict__ logits_out) {
    int warp = threadIdx.x >> 5;
    int lane = threadIdx.x & 31;
    int t = blockIdx.x * 4 + warp;
    if (t >= T_TOK) return;

    float acc[9];
#pragma unroll
    for (int i = 0; i < 9; i++) acc[i] = 0.f;

    const float4* hp = (const float4*)(h + (size_t)t * DDIM);
    __half2* hp16 = (__half2*)(g_h16 + (size_t)t * DDIM);
    for (int d = lane; d < DDIM / 4; d += 32) {
        float4 hv = hp[d];
        hp16[d * 2]     = __floats2half2_rn(hv.x, hv.y);
        hp16[d * 2 + 1] = __floats2half2_rn(hv.z, hv.w);
#pragma unroll
        for (int e = 0; e < NEXP; e++) {
            float4 w = ((const float4*)(gate_w + (size_t)e * DDIM))[d];
            acc[e] += hv.x * w.x + hv.y * w.y + hv.z * w.z + hv.w * w.w;
        }
        float4 w = ((const float4*)sg_w)[d];
        acc[8] += hv.x * w.x + hv.y * w.y + hv.z * w.z + hv.w * w.w;
    }
#pragma unroll
    for (int i = 0; i < 9; i++) {
#pragma unroll
        for (int off = 16; off > 0; off >>= 1)
            acc[i] += __shfl_down_sync(0xffffffffu, acc[i], off);
    }

    if (lane == 0) {
        if (logits_out) {
#pragma unroll
            for (int e = 0; e < NEXP; e++) logits_out[t * NEXP + e] = acc[e];
        }
        int i0 = 0;
#pragma unroll
        for (int e = 1; e < NEXP; e++) if (acc[e] > acc[i0]) i0 = e;
        int i1 = (i0 == 0) ? 1 : 0;
#pragma unroll
        for (int e = 0; e < NEXP; e++) if (e != i0 && e != i1 && acc[e] > acc[i1]) i1 = e;

        float wA = 1.f / (1.f + expf(acc[i1] - acc[i0]));
        float wB = 1.f - wA;

        int s0 = atomicAdd(&g_cnt[i0], 1);
        g_tok[i0 * CAP + s0] = t;  g_wt[i0 * CAP + s0] = wA;
        int s1 = atomicAdd(&g_cnt[i1], 1);
        g_tok[i1 * CAP + s1] = t;  g_wt[i1 * CAP + s1] = wB;

        g_gate[t] = 1.f / (1.f + expf(-acc[8]));
    }
}

// ---------------------------------------------------------------------------
// MERGED fused up-projection (routed experts z=0..7, shared z=8).
// One pass computes g and u; SwiGLU in registers; fp16 out.
// CTA 128(M) x 64(N), 256 threads = 8 warps (4x2), warp tile 32x32 dual.
// 3-stage cp.async pipeline, ONE __syncthreads per k-iteration.
// ---------------------------------------------------------------------------
__global__ void __launch_bounds__(256, 2)
upfused_h(const __half* __restrict__ A,
          const __half* __restrict__ W0g, const float* __restrict__ B0r,
          const __half* __restrict__ W1g, const float* __restrict__ B1r,
          const float* __restrict__ SB0, const float* __restrict__ SB1,
          const __half* __restrict__ SW0, const __half* __restrict__ SW1) {
    constexpr int NT = DDIM / BKH;   // 64
    const bool routed = (blockIdx.z < NEXP);
    const int e  = routed ? blockIdx.z : 0;
    const int Ne = routed ? g_cnt[e] : T_TOK;
    const int row0 = blockIdx.y * BM;
    if (row0 >= Ne) return;
    const int n0  = blockIdx.x * BNF;
    const int tid  = threadIdx.x;
    const int lane = tid & 31;
    const int wid  = tid >> 5;
    const int wm   = (wid >> 1) * 32;
    const int wn   = (wid & 1) * 32;

    extern __shared__ char dyn[];
    __shared__ int sTok[BM];

    if (tid < BM) {
        int r = row0 + tid;
        sTok[tid] = routed ? g_tok[e * CAP + ((r < Ne) ? r : (Ne - 1))] : (row0 + tid);
    }
    __syncthreads();

    const __half* W0b = routed ? (W0g + (size_t)e * FDIM * DDIM) : SW0;
    const __half* W1b = routed ? (W1g + (size_t)e * FDIM * DDIM) : SW1;

    float acc0[2][4][4], acc1[2][4][4];
#pragma unroll
    for (int i = 0; i < 2; i++)
#pragma unroll
        for (int j = 0; j < 4; j++)
#pragma unroll
            for (int r = 0; r < 4; r++) { acc0[i][j][r] = 0.f; acc1[i][j][r] = 0.f; }

    // staging coords: A = 512 chunks (2/thread), B0/B1 = 256 chunks (1/thread)
    const __half* aptr[2];
    uint32_t offA[2];
#pragma unroll
    for (int i = 0; i < 2; i++) {
        int idx = i * 256 + tid;
        int r  = idx >> 2;
        int ch = (idx & 3) * 8;
        aptr[i] = A + (size_t)sTok[r] * DDIM + ch;
        offA[i] = (uint32_t)((r * SPAD + (idx & 3) * 4) * 4);
    }
    const int br  = tid >> 2;
    const int bch = (tid & 3) * 8;
    const __half* b0ptr = W0b + (size_t)(n0 + br) * DDIM + bch;
    const __half* b1ptr = W1b + (size_t)(n0 + br) * DDIM + bch;
    const uint32_t offB = (uint32_t)((br * SPAD + (tid & 3) * 4) * 4);

    const uint32_t dbase = su32(dyn);
    const uint32_t offB0 = BM * SPAD * 4;            // B0 after A
    const uint32_t offB1 = offB0 + BNF * SPAD * 4;   // B1 after B0

    // prologue: stages 0, 1
#pragma unroll
    for (int s = 0; s < 2; s++) {
        const uint32_t sb = dbase + s * STGU;
        const int koff = s * BKH;
#pragma unroll
        for (int i = 0; i < 2; i++) cpasync16(sb + offA[i], aptr[i] + koff);
        cpasync16(sb + offB0 + offB, b0ptr + koff);
        cpasync16(sb + offB1 + offB, b1ptr + koff);
        CP_COMMIT();
    }

    int sel = 0;
    for (int it = 0; it < NT; it++) {
        CP_WAIT1();
        __syncthreads();
        if (it + 2 < NT) {
            int ns = sel + 2; if (ns >= NSTG) ns -= NSTG;
            const uint32_t sb = dbase + ns * STGU;
            const int koff = (it + 2) * BKH;
#pragma unroll
            for (int i = 0; i < 2; i++) cpasync16(sb + offA[i], aptr[i] + koff);
            cpasync16(sb + offB0 + offB, b0ptr + koff);
            cpasync16(sb + offB1 + offB, b1ptr + koff);
            CP_COMMIT();
        }

        const uint32_t* As  = (const uint32_t*)(dyn + sel * STGU);
        const uint32_t* Bs0 = As + BM * SPAD;
        const uint32_t* Bs1 = Bs0 + BNF * SPAD;
        const int lr = lane >> 2, lc = lane & 3;
#pragma unroll
        for (int ks = 0; ks < 2; ks++) {
            const int base = ks * 8;
            uint32_t af[2][4], bf0[4][2], bf1[4][2];
#pragma unroll
            for (int im = 0; im < 2; im++) {
                int rb = wm + im * 16 + lr;
                af[im][0] = As[rb * SPAD + base + lc];
                af[im][1] = As[(rb + 8) * SPAD + base + lc];
                af[im][2] = As[rb * SPAD + base + lc + 4];
                af[im][3] = As[(rb + 8) * SPAD + base + lc + 4];
            }
#pragma unroll
            for (int in = 0; in < 4; in++) {
                int nb = wn + in * 8 + lr;
                bf0[in][0] = Bs0[nb * SPAD + base + lc];
                bf0[in][1] = Bs0[nb * SPAD + base + lc + 4];
                bf1[in][0] = Bs1[nb * SPAD + base + lc];
                bf1[in][1] = Bs1[nb * SPAD + base + lc + 4];
            }
#pragma unroll
            for (int im = 0; im < 2; im++)
#pragma unroll
                for (int in = 0; in < 4; in++) {
                    mma16(acc0[im][in], af[im], bf0[in]);
                    mma16(acc1[im][in], af[im], bf1[in]);
                }
        }
        sel++; if (sel >= NSTG) sel = 0;
    }

    // ---- epilogue: SwiGLU fully in registers, fp16 out ----
    const float* b0p = routed ? (B0r + e * FDIM) : SB0;
    const float* b1p = routed ? (B1r + e * FDIM) : SB1;
#pragma unroll
    for (int im = 0; im < 2; im++) {
#pragma unroll
        for (int in = 0; in < 4; in++) {
            const int c0 = n0 + wn + in * 8 + 2 * (lane & 3);
            const float g_b0 = b0p[c0], g_b1 = b0p[c0 + 1];
            const float u_b0 = b1p[c0], u_b1 = b1p[c0 + 1];
#pragma unroll
            for (int hr = 0; hr < 2; hr++) {
                int r = wm + im * 16 + (lane >> 2) + hr * 8;
                if (row0 + r >= Ne) continue;
                float gg0 = acc0[im][in][hr * 2 + 0] + g_b0;
                float gg1 = acc0[im][in][hr * 2 + 1] + g_b1;
                float uu0 = acc1[im][in][hr * 2 + 0] + u_b0;
                float uu1 = acc1[im][in][hr * 2 + 1] + u_b1;
                float r0 = silu(gg0) * uu0;
                float r1 = silu(gg1) * uu1;
                if (routed) {
                    size_t idx = ((size_t)e * CAP + row0 + r) * FDIM + c0;
                    *(__half2*)(g_ih + idx) = __floats2half2_rn(r0, r1);
                } else {
                    size_t idx = (size_t)(row0 + r) * FDIM + c0;
                    *(__half2*)(g_sih + idx) = __floats2half2_rn(r0, r1);
                }
            }
        }
    }
}

// ---------------------------------------------------------------------------
// Down-projection fp16 mma.sync GEMM, 3-stage cp.async, one barrier per iter.
// CTA 128x128, 256 threads = 8 warps (2x4), warp tile 64x32, K=FDIM.
// MODE 2: routed  A=g_ih;  atomicAdd(out[tok,d], wt*(acc+bo[e,d]))
// MODE 3: shared  A=g_sih; out[t,d] = gate[t]*(acc+sbo[d])
// ---------------------------------------------------------------------------
template<int MODE>
__global__ void __launch_bounds__(256, 2)
gemm_h(const __half* __restrict__ A, const __half* __restrict__ B,
       const float* __restrict__ bias, float* __restrict__ out) {
    constexpr int K  = FDIM;
    constexpr int NT = K / BKH;   // 16
    const int e  = (MODE == 2) ? blockIdx.z : 0;
    const int Ne = (MODE == 2) ? g_cnt[e] : T_TOK;
    const int row0 = blockIdx.y * BM;
    if (row0 >= Ne) return;
    const int n0  = blockIdx.x * BN;
    const int tid  = threadIdx.x;
    const int lane = tid & 31;
    const int wid  = tid >> 5;
    const int wm   = (wid >> 2) * 64;
    const int wn   = (wid & 3) * 32;

    extern __shared__ char dyn[];
    __shared__ int   sTok[BM];
    __shared__ float sWt[BM];

    if (MODE == 2) {
        if (tid < BM) {
            int r = row0 + tid;
            int rr = (r < Ne) ? r : (Ne - 1);
            sTok[tid] = g_tok[e * CAP + rr];
            sWt[tid]  = g_wt[e * CAP + rr];
        }
        __syncthreads();
    }

    const __half* Bb = (MODE == 2) ? (B + (size_t)e * DDIM * FDIM) : B;

    float acc[4][4][4];
#pragma unroll
    for (int i = 0; i < 4; i++)
#pragma unroll
        for (int j = 0; j < 4; j++)
#pragma unroll
            for (int r = 0; r < 4; r++) acc[i][j][r] = 0.f;

    const __half* aptr[2];
    const __half* bptr[2];
    uint32_t      offA[2];
#pragma unroll
    for (int i = 0; i < 2; i++) {
        int idx = i * 256 + tid;
        int r  = idx >> 2;
        int ch = (idx & 3) * 8;
        if (MODE == 2) aptr[i] = A + ((size_t)e * CAP + row0 + r) * FDIM + ch;
        else           aptr[i] = A + (size_t)(row0 + r) * FDIM + ch;
        bptr[i] = Bb + (size_t)(n0 + r) * K + ch;
        offA[i] = (uint32_t)((r * SPAD + (idx & 3) * 4) * 4);
    }

    const uint32_t dbase = su32(dyn);
    const uint32_t offBt = BM * SPAD * 4;

    // prologue: stages 0, 1
#pragma unroll
    for (int s = 0; s < 2; s++) {
        const uint32_t sb = dbase + s * STGD;
        const int koff = s * BKH;
#pragma unroll
        for (int i = 0; i < 2; i++) {
            cpasync16(sb + offA[i],         aptr[i] + koff);
            cpasync16(sb + offBt + offA[i], bptr[i] + koff);
        }
        CP_COMMIT();
    }

    int sel = 0;
    for (int it = 0; it < NT; it++) {
        CP_WAIT1();
        __syncthreads();
        if (it + 2 < NT) {
            int ns = sel + 2; if (ns >= NSTG) ns -= NSTG;
            const uint32_t sb = dbase + ns * STGD;
            const int koff = (it + 2) * BKH;
#pragma unroll
            for (int i = 0; i < 2; i++) {
                cpasync16(sb + offA[i],         aptr[i] + koff);
                cpasync16(sb + offBt + offA[i], bptr[i] + koff);
            }
            CP_COMMIT();
        }

        const uint32_t* As = (const uint32_t*)(dyn + sel * STGD);
        const uint32_t* Bs = As + BM * SPAD;
        const int lr = lane >> 2, lc = lane & 3;
#pragma unroll
        for (int ks = 0; ks < 2; ks++) {
            const int base = ks * 8;
            uint32_t af[4][4], bf[4][2];
#pragma unroll
            for (int im = 0; im < 4; im++) {
                int rb = wm + im * 16 + lr;
                af[im][0] = As[rb * SPAD + base + lc];
                af[im][1] = As[(rb + 8) * SPAD + base + lc];
                af[im][2] = As[rb * SPAD + base + lc + 4];
                af[im][3] = As[(rb + 8) * SPAD + base + lc + 4];
            }
#pragma unroll
            for (int in = 0; in < 4; in++) {
                int nb = wn + in * 8 + lr;
                bf[in][0] = Bs[nb * SPAD + base + lc];
                bf[in][1] = Bs[nb * SPAD + base + lc + 4];
            }
#pragma unroll
            for (int im = 0; im < 4; im++)
#pragma unroll
                for (int in = 0; in < 4; in++)
                    mma16(acc[im][in], af[im], bf[in]);
        }
        sel++; if (sel >= NSTG) sel = 0;
    }

    const float* bp = (MODE == 2) ? (bias + e * DDIM) : bias;
#pragma unroll
    for (int im = 0; im < 4; im++) {
#pragma unroll
        for (int in = 0; in < 4; in++) {
            const int c0 = n0 + wn + in * 8 + 2 * (lane & 3);
            const float b0v = bp[c0], b1v = bp[c0 + 1];
#pragma unroll
            for (int hr = 0; hr < 2; hr++) {
                int r = wm + im * 16 + (lane >> 2) + hr * 8;
                if (row0 + r >= Ne) continue;
                float v0 = acc[im][in][hr * 2 + 0] + b0v;
                float v1 = acc[im][in][hr * 2 + 1] + b1v;
                if (MODE == 2) {
                    int   t  = sTok[r];
                    float wt = sWt[r];
                    float* op = out + (size_t)t * DDIM + c0;
                    atomicAdd(op,     wt * v0);
                    atomicAdd(op + 1, wt * v1);
                } else {
                    float gate = g_gate[row0 + r];
                    *(float2*)(out + (size_t)(row0 + r) * DDIM + c0) =
                        make_float2(gate * v0, gate * v1);
                }
            }
        }
    }
}

// ---------------------------------------------------------------------------
#define SMEM_UPK (NSTG * STGU)   // 61440
#define SMEM_DNK (NSTG * STGD)   // 61440

extern "C" void kernel_launch(void* const* d_in, const int* in_sizes, int n_in,
                              void* d_out, int out_size) {
    const float* h      = (const float*)d_in[0];
    const float* gate_w = (const float*)d_in[1];
    const float* w0     = (const float*)d_in[2];
    const float* b0     = (const float*)d_in[3];
    const float* w1     = (const float*)d_in[4];
    const float* b1     = (const float*)d_in[5];
    const float* wo     = (const float*)d_in[6];
    const float* bo     = (const float*)d_in[7];
    const float* sw0    = (const float*)d_in[8];
    const float* sb0    = (const float*)d_in[9];
    const float* sw1    = (const float*)d_in[10];
    const float* sb1    = (const float*)d_in[11];
    const float* swo    = (const float*)d_in[12];
    const float* sbo    = (const float*)d_in[13];
    const float* sg_w   = (const float*)d_in[14];

    float* out = (float*)d_out;
    float* logits = nullptr;
    if ((size_t)out_size >= (size_t)T_TOK * DDIM + (size_t)T_TOK * NEXP)
        logits = out + (size_t)T_TOK * DDIM;

    __half *h16, *w0h, *w1h, *woh, *sw0h, *sw1h, *swoh, *ih, *sih;
    cudaGetSymbolAddress((void**)&h16,  g_h16);
    cudaGetSymbolAddress((void**)&w0h,  g_w0h);
    cudaGetSymbolAddress((void**)&w1h,  g_w1h);
    cudaGetSymbolAddress((void**)&woh,  g_woh);
    cudaGetSymbolAddress((void**)&sw0h, g_sw0h);
    cudaGetSymbolAddress((void**)&sw1h, g_sw1h);
    cudaGetSymbolAddress((void**)&swoh, g_swoh);
    cudaGetSymbolAddress((void**)&ih,   g_ih);
    cudaGetSymbolAddress((void**)&sih,  g_sih);

    cudaFuncSetAttribute(upfused_h, cudaFuncAttributeMaxDynamicSharedMemorySize, SMEM_UPK);
    cudaFuncSetAttribute(gemm_h<2>, cudaFuncAttributeMaxDynamicSharedMemorySize, SMEM_DNK);
    cudaFuncSetAttribute(gemm_h<3>, cudaFuncAttributeMaxDynamicSharedMemorySize, SMEM_DNK);

    zero_counts_kernel<<<1, 32>>>();
    router_kernel<<<T_TOK / 4, 128>>>(h, gate_w, sg_w, logits);   // also emits h16

    // weight fp32 -> fp16 conversion (bandwidth-bound)
    const unsigned NB_W = (unsigned)((size_t)NEXP * FDIM * DDIM / 4 / 256);
    const unsigned NB_S = (unsigned)((size_t)FDIM * DDIM / 4 / 256);
    cvt_half_kernel<<<NB_W, 256>>>(w0,  w0h);
    cvt_half_kernel<<<NB_W, 256>>>(w1,  w1h);
    cvt_half_kernel<<<NB_W, 256>>>(wo,  woh);
    cvt_half_kernel<<<NB_S, 256>>>(sw0, sw0h);
    cvt_half_kernel<<<NB_S, 256>>>(sw1, sw1h);
    cvt_half_kernel<<<NB_S, 256>>>(swo, swoh);

    // merged fused up projections: z = 0..7 routed experts, z = 8 shared
    upfused_h<<<dim3(FDIM / BNF, CAP / BM, NEXP + 1), 256, SMEM_UPK>>>(
        h16, w0h, b0, w1h, b1, sb0, sb1, sw0h, sw1h);

    // down projections: shared writes base, routed atomically accumulates
    gemm_h<3><<<dim3(DDIM / BN, T_TOK / BM, 1), 256, SMEM_DNK>>>(sih, swoh, sbo, out);
    gemm_h<2><<<dim3(DDIM / BN, CAP / BM, NEXP), 256, SMEM_DNK>>>(ih, woh, bo, out);
}